// round 7
// baseline (speedup 1.0000x reference)
#include <cuda_runtime.h>
#include <cstdint>

// AggrSum: out[n, :] = sum over edges e with X_node[e] == n of H[e, :]
// H: [2M, 32] f32, X_node: [2M] i32 (harness downcast), out: [100K, 32] f32
//
// R7: 2-kernel bucket-CSR.
//   k1 build : pos = atomicAdd(count[n],1); bucket[n*CAP+pos] = e  (8-deep ILP)
//   k2 gather: warp per node, float4 lanes (4 edge rows per LDG.128 wave),
//              shfl_xor cross-subgroup reduce, coalesced 128B store.
//              Resets count[n]=0 after use -> no zeroing kernel needed
//              (__device__ globals start zeroed; every call restores zeros).
// Fallback RED-scatter path for shapes exceeding static scratch.

static constexpr int D = 32;
static constexpr int VEC = 4;
static constexpr int LANES = D / VEC;        // 8 float4s per edge row
static constexpr int CAP = 64;               // max edges/node (Poisson(20): max ~47)
static constexpr int MAX_NODES = 1 << 17;    // 131072 >= 100K

__device__ unsigned g_count[MAX_NODES];
__device__ unsigned g_bucket[(size_t)MAX_NODES * CAP];   // 33.5 MB static scratch

// ---------------- build ----------------

__global__ void __launch_bounds__(256)
build_buckets_kernel(const int* __restrict__ idx, int num_edges, int node_num) {
    const int T = gridDim.x * blockDim.x;
    const int t = blockIdx.x * blockDim.x + threadIdx.x;
    #pragma unroll
    for (int k = 0; k < 8; k++) {
        int e = t + k * T;
        if (e < num_edges) {
            int n = __ldcs(&idx[e]);
            if ((unsigned)n < (unsigned)node_num) {
                unsigned p = atomicAdd(&g_count[n], 1u);
                if (p < CAP) g_bucket[(size_t)n * CAP + p] = (unsigned)e;
            }
        }
    }
}

// ---------------- gather ----------------

__global__ void __launch_bounds__(256)
gather_kernel(const float4* __restrict__ H4, float4* __restrict__ out4,
              int node_num) {
    const int warp = (blockIdx.x * blockDim.x + threadIdx.x) >> 5;
    const int lane = threadIdx.x & 31;
    if (warp >= node_num) return;

    unsigned cnt = g_count[warp];
    if (lane == 0) g_count[warp] = 0u;     // restore invariant for next call
    if (cnt > CAP) cnt = CAP;

    const uint4* b4 = reinterpret_cast<const uint4*>(&g_bucket[(size_t)warp * CAP]);
    const int sub = lane >> 3;             // which of 4 edges in a load wave
    const int off = lane & 7;              // float4 offset within the 32-f row

    float4 acc = make_float4(0.f, 0.f, 0.f, 0.f);
    unsigned j = 0;

    // 16 edges per chunk: 4 broadcast uint4 id loads + 16 row-waves in flight.
    for (; j + 16 <= cnt; j += 16) {
        uint4 ids[4];
        #pragma unroll
        for (int q = 0; q < 4; q++) ids[q] = b4[(j >> 2) + q];
        #pragma unroll
        for (int q = 0; q < 4; q++) {
            unsigned e = (sub == 0) ? ids[q].x : (sub == 1) ? ids[q].y
                       : (sub == 2) ? ids[q].z : ids[q].w;
            float4 v = __ldcs(&H4[(size_t)e * LANES + off]);
            acc.x += v.x; acc.y += v.y; acc.z += v.z; acc.w += v.w;
        }
    }
    // Tail: 4 edges at a time with per-subgroup validity predicate.
    for (; j < cnt; j += 4) {
        uint4 id = b4[j >> 2];
        unsigned e = (sub == 0) ? id.x : (sub == 1) ? id.y
                   : (sub == 2) ? id.z : id.w;
        if (j + (unsigned)sub < cnt) {
            float4 v = __ldcs(&H4[(size_t)e * LANES + off]);
            acc.x += v.x; acc.y += v.y; acc.z += v.z; acc.w += v.w;
        }
    }
    __syncwarp();

    // Combine the 4 edge-subgroups: lanes {l, l^8, l^16, l^24}.
    #pragma unroll
    for (int s = 8; s <= 16; s <<= 1) {
        acc.x += __shfl_xor_sync(0xFFFFFFFFu, acc.x, s);
        acc.y += __shfl_xor_sync(0xFFFFFFFFu, acc.y, s);
        acc.z += __shfl_xor_sync(0xFFFFFFFFu, acc.z, s);
        acc.w += __shfl_xor_sync(0xFFFFFFFFu, acc.w, s);
    }
    if (sub == 0) out4[(size_t)warp * LANES + off] = acc;   // 128B coalesced
}

// ---------------- fallback scatter (shapes beyond static scratch) ----------------

__global__ void zero_out_kernel(float4* __restrict__ out, int n4) {
    int T = gridDim.x * blockDim.x;
    for (int i = blockIdx.x * blockDim.x + threadIdx.x; i < n4; i += T)
        out[i] = make_float4(0.f, 0.f, 0.f, 0.f);
}

__global__ void __launch_bounds__(128)
scatter_add_kernel(const float4* __restrict__ H, const int* __restrict__ idx,
                   float* __restrict__ out, int nitems, int node_num) {
    const int T = gridDim.x * blockDim.x;
    const int t = blockIdx.x * blockDim.x + threadIdx.x;
    #pragma unroll
    for (int k = 0; k < 8; k++) {
        int i = t + k * T;
        if (i < nitems) {
            float4 v = __ldcs(&H[i]);
            int n = __ldg(&idx[i >> 3]);
            if ((unsigned)n < (unsigned)node_num) {
                float* dst = out + (size_t)(unsigned)n * D + (i & (LANES - 1)) * VEC;
                asm volatile("red.global.add.v4.f32 [%0], {%1, %2, %3, %4};"
                             :: "l"(dst), "f"(v.x), "f"(v.y), "f"(v.z), "f"(v.w)
                             : "memory");
            }
        }
    }
}

extern "C" void kernel_launch(void* const* d_in, const int* in_sizes, int n_in,
                              void* d_out, int out_size) {
    const float* H = (const float*)d_in[0];
    const int* idx = (const int*)d_in[1];
    float* out = (float*)d_out;

    int num_edges = in_sizes[0] / D;
    int node_num = out_size / D;

    if (node_num <= MAX_NODES) {
        {   // build: 8 edges/thread
            long long want = ((long long)num_edges + 7) / 8;
            int blocks = (int)((want + 255) / 256);
            build_buckets_kernel<<<blocks, 256>>>(idx, num_edges, node_num);
        }
        {   // gather: warp per node (also resets counts)
            long long threads = (long long)node_num * 32;
            int blocks = (int)((threads + 255) / 256);
            gather_kernel<<<blocks, 256>>>((const float4*)H, (float4*)out, node_num);
        }
    } else {
        int nitems = num_edges * LANES;
        {
            int n4 = out_size / VEC;
            int blocks = (n4 + 255) / 256;
            if (blocks > 3200) blocks = 3200;
            zero_out_kernel<<<blocks, 256>>>((float4*)out, n4);
        }
        {
            long long want = ((long long)nitems + 7) / 8;
            int blocks = (int)((want + 127) / 128);
            scatter_add_kernel<<<blocks, 128>>>((const float4*)H, idx, out,
                                                nitems, node_num);
        }
    }
}

// round 8
// speedup vs baseline: 1.2030x; 1.2030x over previous
#include <cuda_runtime.h>
#include <cstdint>

// AggrSum: out[n, :] = sum over edges e with X_node[e] == n of H[e, :]
// H: [2M, 32] f32, X_node: [2M] i32 (harness downcast), out: [100K, 32] f32
//
// R8: bucket-CSR with latency-flattened gather.
//   build : 8 consecutive edges/thread (2x int4 idx loads), thin ATOMG place.
//   gather: warp per node. ALL 64 bucket ids loaded up-front (2 coalesced
//           LDG.128), distributed to edge-subgroups via shfl -> every row
//           load independent and issuable after one latency. Uniform
//           predicated wave loop (no serial tail). Resets counts (globals
//           start zeroed; every call restores zeros -> replay-safe).

static constexpr int D = 32;
static constexpr int VEC = 4;
static constexpr int LANES = D / VEC;        // 8 float4s per edge row
static constexpr int CAP = 64;               // max edges/node (Poisson(20): max ~47)
static constexpr int MAX_NODES = 1 << 17;    // 131072 >= 100K

__device__ unsigned g_count[MAX_NODES];
__device__ unsigned g_bucket[(size_t)MAX_NODES * CAP];   // 33.5 MB static scratch

// ---------------- build ----------------

__global__ void __launch_bounds__(256)
build_buckets_kernel(const int* __restrict__ idx, int num_edges, int node_num) {
    int t = blockIdx.x * blockDim.x + threadIdx.x;
    int e0 = t * 8;
    if (e0 + 8 <= num_edges) {
        const int4* p = reinterpret_cast<const int4*>(idx + e0);
        int4 a = __ldcs(&p[0]);
        int4 c = __ldcs(&p[1]);
        int n[8] = {a.x, a.y, a.z, a.w, c.x, c.y, c.z, c.w};
        #pragma unroll
        for (int k = 0; k < 8; k++) {
            if ((unsigned)n[k] < (unsigned)node_num) {
                unsigned p2 = atomicAdd(&g_count[n[k]], 1u);
                if (p2 < CAP) g_bucket[(size_t)n[k] * CAP + p2] = (unsigned)(e0 + k);
            }
        }
    } else {
        for (int e = e0; e < num_edges; e++) {
            int n = __ldcs(&idx[e]);
            if ((unsigned)n < (unsigned)node_num) {
                unsigned p2 = atomicAdd(&g_count[n], 1u);
                if (p2 < CAP) g_bucket[(size_t)n * CAP + p2] = (unsigned)e;
            }
        }
    }
}

// ---------------- gather ----------------

__global__ void __launch_bounds__(256)
gather_kernel(const float4* __restrict__ H4, float4* __restrict__ out4,
              int node_num) {
    const int warp = (blockIdx.x * blockDim.x + threadIdx.x) >> 5;
    const int lane = threadIdx.x & 31;
    if (warp >= node_num) return;

    // All independent loads issued immediately: 64 ids + count.
    const unsigned* b = &g_bucket[(size_t)warp * CAP];
    unsigned id_lo = b[lane];          // coalesced 128B (may hold stale ids)
    unsigned id_hi = b[lane + 32];     // coalesced 128B
    unsigned cnt = g_count[warp];
    if (lane == 0) g_count[warp] = 0u; // restore invariant for next call
    if (cnt > CAP) cnt = CAP;

    const int sub = lane >> 3;         // edge slot within a 4-edge wave
    const int off = lane & 7;          // float4 offset within the 32-f row

    float4 acc = make_float4(0.f, 0.f, 0.f, 0.f);

    // 16 waves max, 4 edges/wave; 4 waves unrolled per iteration, all loads
    // front-batched and predicated (warp-uniform trip count, no divergence).
    #pragma unroll 1
    for (unsigned w = 0; w < CAP / 4; w += 4) {
        if (w * 4 >= cnt) break;       // uniform
        float4 v[4];
        bool ok[4];
        #pragma unroll
        for (int q = 0; q < 4; q++) {
            unsigned wave = w + q;
            unsigned j = wave * 4 + (unsigned)sub;          // edge index
            unsigned src = (wave < 8) ? id_lo : id_hi;
            unsigned eid = __shfl_sync(0xFFFFFFFFu, src, (int)(j & 31));
            ok[q] = (j < cnt);
            if (ok[q]) v[q] = __ldcs(&H4[(size_t)eid * LANES + off]);
        }
        #pragma unroll
        for (int q = 0; q < 4; q++) {
            if (ok[q]) {
                acc.x += v[q].x; acc.y += v[q].y;
                acc.z += v[q].z; acc.w += v[q].w;
            }
        }
    }

    // Combine the 4 edge-subgroups: lanes {l, l^8, l^16, l^24}.
    #pragma unroll
    for (int s = 8; s <= 16; s <<= 1) {
        acc.x += __shfl_xor_sync(0xFFFFFFFFu, acc.x, s);
        acc.y += __shfl_xor_sync(0xFFFFFFFFu, acc.y, s);
        acc.z += __shfl_xor_sync(0xFFFFFFFFu, acc.z, s);
        acc.w += __shfl_xor_sync(0xFFFFFFFFu, acc.w, s);
    }
    if (sub == 0) out4[(size_t)warp * LANES + off] = acc;   // 128B coalesced
}

// ---------------- fallback scatter (shapes beyond static scratch) ----------------

__global__ void zero_out_kernel(float4* __restrict__ out, int n4) {
    int T = gridDim.x * blockDim.x;
    for (int i = blockIdx.x * blockDim.x + threadIdx.x; i < n4; i += T)
        out[i] = make_float4(0.f, 0.f, 0.f, 0.f);
}

__global__ void __launch_bounds__(128)
scatter_add_kernel(const float4* __restrict__ H, const int* __restrict__ idx,
                   float* __restrict__ out, int nitems, int node_num) {
    const int T = gridDim.x * blockDim.x;
    const int t = blockIdx.x * blockDim.x + threadIdx.x;
    #pragma unroll
    for (int k = 0; k < 8; k++) {
        int i = t + k * T;
        if (i < nitems) {
            float4 v = __ldcs(&H[i]);
            int n = __ldg(&idx[i >> 3]);
            if ((unsigned)n < (unsigned)node_num) {
                float* dst = out + (size_t)(unsigned)n * D + (i & (LANES - 1)) * VEC;
                asm volatile("red.global.add.v4.f32 [%0], {%1, %2, %3, %4};"
                             :: "l"(dst), "f"(v.x), "f"(v.y), "f"(v.z), "f"(v.w)
                             : "memory");
            }
        }
    }
}

extern "C" void kernel_launch(void* const* d_in, const int* in_sizes, int n_in,
                              void* d_out, int out_size) {
    const float* H = (const float*)d_in[0];
    const int* idx = (const int*)d_in[1];
    float* out = (float*)d_out;

    int num_edges = in_sizes[0] / D;
    int node_num = out_size / D;

    if (node_num <= MAX_NODES) {
        {   // build: 8 consecutive edges per thread
            long long want = ((long long)num_edges + 7) / 8;
            int blocks = (int)((want + 255) / 256);
            build_buckets_kernel<<<blocks, 256>>>(idx, num_edges, node_num);
        }
        {   // gather: warp per node (also resets counts)
            long long threads = (long long)node_num * 32;
            int blocks = (int)((threads + 255) / 256);
            gather_kernel<<<blocks, 256>>>((const float4*)H, (float4*)out, node_num);
        }
    } else {
        int nitems = num_edges * LANES;
        {
            int n4 = out_size / VEC;
            int blocks = (n4 + 255) / 256;
            if (blocks > 3200) blocks = 3200;
            zero_out_kernel<<<blocks, 256>>>((float4*)out, n4);
        }
        {
            long long want = ((long long)nitems + 7) / 8;
            int blocks = (int)((want + 127) / 128);
            scatter_add_kernel<<<blocks, 128>>>((const float4*)H, idx, out,
                                                nitems, node_num);
        }
    }
}

// round 9
// speedup vs baseline: 2.6256x; 2.1825x over previous
#include <cuda_runtime.h>
#include <cstdint>

// AggrSum: out[n, :] = sum over edges e with X_node[e] == n of H[e, :]
// H: [2M, 32] f32, X_node: [2M] i32 (harness downcast), out: [100K, 32] f32
//
// R9: bucket-CSR, gather v3.
//   build : 8 consecutive edges/thread (2x int4 idx loads), thin ATOMG place.
//   gather: 4 nodes per warp; 8-lane group owns a node end-to-end.
//           Row load = one 128B line; node result stored directly (no shfl
//           reduction). Ids prefetched one 8-edge chunk ahead in scalar regs.
//           Resets counts (device globals start zeroed; every call restores
//           zeros -> graph-replay safe). Gather overwrites every output row,
//           so no zeroing kernel is needed.

static constexpr int D = 32;
static constexpr int VEC = 4;
static constexpr int LANES = D / VEC;        // 8 float4s per edge row
static constexpr int CAP = 64;               // max edges/node (Poisson(20): max ~47)
static constexpr int MAX_NODES = 1 << 17;    // 131072 >= 100K

__device__ unsigned g_count[MAX_NODES];
__device__ unsigned g_bucket[(size_t)MAX_NODES * CAP];   // 33.5 MB static scratch

// ---------------- build ----------------

__global__ void __launch_bounds__(256)
build_buckets_kernel(const int* __restrict__ idx, int num_edges, int node_num) {
    int t = blockIdx.x * blockDim.x + threadIdx.x;
    int e0 = t * 8;
    if (e0 + 8 <= num_edges) {
        const int4* p = reinterpret_cast<const int4*>(idx + e0);
        int4 a = __ldcs(&p[0]);
        int4 c = __ldcs(&p[1]);
        int n[8] = {a.x, a.y, a.z, a.w, c.x, c.y, c.z, c.w};
        #pragma unroll
        for (int k = 0; k < 8; k++) {
            if ((unsigned)n[k] < (unsigned)node_num) {
                unsigned p2 = atomicAdd(&g_count[n[k]], 1u);
                if (p2 < CAP) g_bucket[(size_t)n[k] * CAP + p2] = (unsigned)(e0 + k);
            }
        }
    } else {
        for (int e = e0; e < num_edges; e++) {
            int n = __ldcs(&idx[e]);
            if ((unsigned)n < (unsigned)node_num) {
                unsigned p2 = atomicAdd(&g_count[n], 1u);
                if (p2 < CAP) g_bucket[(size_t)n * CAP + p2] = (unsigned)e;
            }
        }
    }
}

// ---------------- gather v3 ----------------

__global__ void __launch_bounds__(256)
gather_kernel(const float4* __restrict__ H4, float4* __restrict__ out4,
              int node_num) {
    const int warp = (blockIdx.x * blockDim.x + threadIdx.x) >> 5;
    const int lane = threadIdx.x & 31;
    const int g   = lane >> 3;      // node slot within warp (0..3)
    const int off = lane & 7;       // float4 offset within the 32-float row

    const int node = warp * 4 + g;
    const bool valid = (node < node_num);

    unsigned cnt = 0;
    if (valid) cnt = g_count[node];            // 8-lane broadcast load
    if (valid && off == 0) g_count[node] = 0u; // restore invariant for replay
    if (cnt > CAP) cnt = CAP;

    // Warp-uniform trip count = max cnt over the 4 groups.
    unsigned m = cnt;
    #pragma unroll
    for (int s = 16; s; s >>= 1)
        m = max(m, __shfl_xor_sync(0xFFFFFFFFu, m, s));

    const unsigned* b = g_bucket + (size_t)node * CAP;
    float4 acc = make_float4(0.f, 0.f, 0.f, 0.f);

    // Ids: lane `off` of each group holds id at position j+off (32B coalesced
    // per group). Prefetched one chunk ahead in a scalar register.
    unsigned idreg = 0;
    if (valid && off < cnt) idreg = b[off];

    for (unsigned j = 0; j < m; j += 8) {
        unsigned nxt = 0;
        if (valid && (j + 8 + (unsigned)off) < cnt) nxt = b[j + 8 + off];

        // 8 independent row loads per group (32 lines in flight per warp).
        #pragma unroll
        for (int k = 0; k < 8; k++) {
            unsigned eid = __shfl_sync(0xFFFFFFFFu, idreg, (g << 3) + k);
            if (j + (unsigned)k < cnt) {
                float4 v = __ldcs(&H4[(size_t)eid * LANES + off]);
                acc.x += v.x; acc.y += v.y; acc.z += v.z; acc.w += v.w;
            }
        }
        idreg = nxt;
    }

    // Direct store: warp writes 4 contiguous node rows = 512B coalesced.
    if (valid) out4[(size_t)node * LANES + off] = acc;
}

// ---------------- fallback scatter (shapes beyond static scratch) ----------------

__global__ void zero_out_kernel(float4* __restrict__ out, int n4) {
    int T = gridDim.x * blockDim.x;
    for (int i = blockIdx.x * blockDim.x + threadIdx.x; i < n4; i += T)
        out[i] = make_float4(0.f, 0.f, 0.f, 0.f);
}

__global__ void __launch_bounds__(128)
scatter_add_kernel(const float4* __restrict__ H, const int* __restrict__ idx,
                   float* __restrict__ out, int nitems, int node_num) {
    const int T = gridDim.x * blockDim.x;
    const int t = blockIdx.x * blockDim.x + threadIdx.x;
    #pragma unroll
    for (int k = 0; k < 8; k++) {
        int i = t + k * T;
        if (i < nitems) {
            float4 v = __ldcs(&H[i]);
            int n = __ldg(&idx[i >> 3]);
            if ((unsigned)n < (unsigned)node_num) {
                float* dst = out + (size_t)(unsigned)n * D + (i & (LANES - 1)) * VEC;
                asm volatile("red.global.add.v4.f32 [%0], {%1, %2, %3, %4};"
                             :: "l"(dst), "f"(v.x), "f"(v.y), "f"(v.z), "f"(v.w)
                             : "memory");
            }
        }
    }
}

extern "C" void kernel_launch(void* const* d_in, const int* in_sizes, int n_in,
                              void* d_out, int out_size) {
    const float* H = (const float*)d_in[0];
    const int* idx = (const int*)d_in[1];
    float* out = (float*)d_out;

    int num_edges = in_sizes[0] / D;
    int node_num = out_size / D;

    if (node_num <= MAX_NODES) {
        {   // build: 8 consecutive edges per thread
            long long want = ((long long)num_edges + 7) / 8;
            int blocks = (int)((want + 255) / 256);
            build_buckets_kernel<<<blocks, 256>>>(idx, num_edges, node_num);
        }
        {   // gather: 4 nodes per warp (also resets counts, writes all rows)
            long long warps = ((long long)node_num + 3) / 4;
            long long threads = warps * 32;
            int blocks = (int)((threads + 255) / 256);
            gather_kernel<<<blocks, 256>>>((const float4*)H, (float4*)out, node_num);
        }
    } else {
        int nitems = num_edges * LANES;
        {
            int n4 = out_size / VEC;
            int blocks = (n4 + 255) / 256;
            if (blocks > 3200) blocks = 3200;
            zero_out_kernel<<<blocks, 256>>>((float4*)out, n4);
        }
        {
            long long want = ((long long)nitems + 7) / 8;
            int blocks = (int)((want + 127) / 128);
            scatter_add_kernel<<<blocks, 128>>>((const float4*)H, idx, out,
                                                nitems, node_num);
        }
    }
}

// round 10
// speedup vs baseline: 3.4028x; 1.2960x over previous
#include <cuda_runtime.h>
#include <cstdint>

// AggrSum: out[n, :] = sum over edges e with X_node[e] == n of H[e, :]
// H: [2M, 32] f32, X_node: [2M] i32 (harness downcast), out: [100K, 32] f32
//
// R10: TMA(bulk-async)-staged scatter. Persistent CTAs stream 256-edge tiles
// (32KB H + 1KB idx) into smem via cp.async.bulk (UBLKCP path — bypasses the
// L1tex/LDG queue), 4-stage mbarrier pipeline; consumers read smem and fire
// red.global.add.v4.f32 (REDG resolves in L2; out is L2-resident).
// Fallback: plain LDG scatter for shapes that break tile alignment.

static constexpr int D = 32;
static constexpr int VEC = 4;
static constexpr int LANES = D / VEC;       // 8 float4s per edge row
static constexpr int TILE_E = 256;          // edges per tile
static constexpr int NSTAGE = 4;
static constexpr int THREADS = 256;
static constexpr int STAGE_H = TILE_E * D * 4;     // 32768 B
static constexpr int STAGE_I = TILE_E * 4;         // 1024 B
static constexpr int STAGE_BYTES = STAGE_H + STAGE_I;   // 33792
static constexpr int SMEM_BYTES = NSTAGE * STAGE_BYTES + 64;  // + mbarriers

// ---------------- helpers ----------------

__device__ __forceinline__ uint32_t smem_u32(const void* p) {
    uint32_t a;
    asm("{ .reg .u64 t; cvta.to.shared.u64 t, %1; cvt.u32.u64 %0, t; }"
        : "=r"(a) : "l"(p));
    return a;
}

__device__ __forceinline__ void mbar_init(uint32_t mbar, uint32_t count) {
    asm volatile("mbarrier.init.shared.b64 [%0], %1;" :: "r"(mbar), "r"(count) : "memory");
}

__device__ __forceinline__ void mbar_expect_tx(uint32_t mbar, uint32_t bytes) {
    asm volatile("mbarrier.arrive.expect_tx.shared.b64 _, [%0], %1;"
                 :: "r"(mbar), "r"(bytes) : "memory");
}

__device__ __forceinline__ void mbar_wait(uint32_t mbar, uint32_t parity) {
    asm volatile(
        "{\n\t"
        ".reg .pred P;\n\t"
        "W_%=:\n\t"
        "mbarrier.try_wait.parity.acquire.cta.shared::cta.b64 P, [%0], %1, 0x989680;\n\t"
        "@P bra D_%=;\n\t"
        "bra W_%=;\n\t"
        "D_%=:\n\t"
        "}"
        :: "r"(mbar), "r"(parity) : "memory");
}

__device__ __forceinline__ void bulk_copy(uint32_t dst_smem, const void* src,
                                          uint32_t bytes, uint32_t mbar) {
    asm volatile(
        "cp.async.bulk.shared::cta.global.mbarrier::complete_tx::bytes "
        "[%0], [%1], %2, [%3];"
        :: "r"(dst_smem), "l"(src), "r"(bytes), "r"(mbar) : "memory");
}

__device__ __forceinline__ void red_add_v4(float* dst, float4 v) {
    asm volatile("red.global.add.v4.f32 [%0], {%1, %2, %3, %4};"
                 :: "l"(dst), "f"(v.x), "f"(v.y), "f"(v.z), "f"(v.w)
                 : "memory");
}

// ---------------- kernels ----------------

__global__ void zero_out_kernel(float4* __restrict__ out, int n4) {
    int T = gridDim.x * blockDim.x;
    for (int i = blockIdx.x * blockDim.x + threadIdx.x; i < n4; i += T)
        out[i] = make_float4(0.f, 0.f, 0.f, 0.f);
}

__global__ void __launch_bounds__(THREADS, 1)
scatter_tma_kernel(const char* __restrict__ Hbase,
                   const char* __restrict__ idxbase,
                   float* __restrict__ out,
                   int num_edges, int node_num, int ntiles) {
    extern __shared__ char smem[];
    const uint32_t sbase = smem_u32(smem);
    const uint32_t mbar0 = sbase + NSTAGE * STAGE_BYTES;   // 8B each
    const int tid = threadIdx.x;

    if (tid < NSTAGE) mbar_init(mbar0 + tid * 8, 1);
    __syncthreads();

    // Prologue: fill all stages.
    if (tid == 0) {
        #pragma unroll
        for (int p = 0; p < NSTAGE; p++) {
            int tile = blockIdx.x + p * gridDim.x;
            if (tile < ntiles) {
                int e0 = tile * TILE_E;
                int ne = min(TILE_E, num_edges - e0);
                uint32_t hb = (uint32_t)ne * 128u;
                uint32_t ib = (uint32_t)ne * 4u;         // 16B-mult (ne%4==0 guaranteed)
                uint32_t mb = mbar0 + p * 8;
                mbar_expect_tx(mb, hb + ib);
                bulk_copy(sbase + p * STAGE_BYTES, Hbase + (size_t)e0 * 128, hb, mb);
                bulk_copy(sbase + p * STAGE_BYTES + STAGE_H, idxbase + (size_t)e0 * 4, ib, mb);
            }
        }
    }

    int k = 0;
    for (int tile = blockIdx.x; tile < ntiles; tile += gridDim.x, k++) {
        const int s = k % NSTAGE;
        const uint32_t ph = (uint32_t)((k / NSTAGE) & 1);
        mbar_wait(mbar0 + s * 8, ph);

        const int e0 = tile * TILE_E;
        const int ne = min(TILE_E, num_edges - e0);
        const float4* Hs = (const float4*)(smem + s * STAGE_BYTES);
        const int*    Is = (const int*)(smem + s * STAGE_BYTES + STAGE_H);

        // 2048 items per tile: item = (edge el, float4 off). 8 items/thread.
        #pragma unroll
        for (int j = 0; j < 8; j++) {
            int item = tid + j * THREADS;
            int el = item >> 3;
            int off = item & 7;
            if (el < ne) {
                int n = Is[el];                       // 8-lane broadcast
                float4 v = Hs[item];                  // conflict-free LDS.128
                if ((unsigned)n < (unsigned)node_num)
                    red_add_v4(out + (size_t)(unsigned)n * D + off * VEC, v);
            }
        }
        __syncthreads();   // all reads of stage s done -> safe to refill

        int nt = tile + NSTAGE * gridDim.x;
        if (tid == 0 && nt < ntiles) {
            int ne2 = min(TILE_E, num_edges - nt * TILE_E);
            uint32_t hb = (uint32_t)ne2 * 128u;
            uint32_t ib = (uint32_t)ne2 * 4u;
            uint32_t mb = mbar0 + s * 8;
            mbar_expect_tx(mb, hb + ib);
            bulk_copy(sbase + s * STAGE_BYTES, Hbase + (size_t)nt * TILE_E * 128, hb, mb);
            bulk_copy(sbase + s * STAGE_BYTES + STAGE_H, idxbase + (size_t)nt * TILE_E * 4, ib, mb);
        }
    }
}

// Fallback: plain LDG scatter (R4 shape) for unaligned edge counts.
__global__ void __launch_bounds__(128)
scatter_ldg_kernel(const float4* __restrict__ H, const int* __restrict__ idx,
                   float* __restrict__ out, int nitems, int node_num) {
    const int T = gridDim.x * blockDim.x;
    const int t = blockIdx.x * blockDim.x + threadIdx.x;
    #pragma unroll
    for (int k = 0; k < 8; k++) {
        int i = t + k * T;
        if (i < nitems) {
            float4 v = __ldcs(&H[i]);
            int n = __ldg(&idx[i >> 3]);
            if ((unsigned)n < (unsigned)node_num)
                red_add_v4(out + (size_t)(unsigned)n * D + (i & (LANES - 1)) * VEC, v);
        }
    }
}

extern "C" void kernel_launch(void* const* d_in, const int* in_sizes, int n_in,
                              void* d_out, int out_size) {
    const float* H = (const float*)d_in[0];
    const int* idx = (const int*)d_in[1];
    float* out = (float*)d_out;

    int num_edges = in_sizes[0] / D;
    int node_num = out_size / D;

    // 1) zero output (poisoned to 0xAA). 12.8 MB.
    {
        int n4 = out_size / VEC;
        int blocks = (n4 + 511) / 512;
        if (blocks > 1184) blocks = 1184;
        zero_out_kernel<<<blocks, 512>>>((float4*)d_out, n4);
    }

    // 2) scatter
    if ((num_edges & 3) == 0) {      // idx tile bytes must be 16B multiples
        static bool attr_set = false;
        if (!attr_set) {
            cudaFuncSetAttribute(scatter_tma_kernel,
                                 cudaFuncAttributeMaxDynamicSharedMemorySize,
                                 SMEM_BYTES);
            attr_set = true;
        }
        int ntiles = (num_edges + TILE_E - 1) / TILE_E;
        int grid = ntiles < 148 ? ntiles : 148;
        scatter_tma_kernel<<<grid, THREADS, SMEM_BYTES>>>(
            (const char*)H, (const char*)idx, out, num_edges, node_num, ntiles);
    } else {
        int nitems = num_edges * LANES;
        long long want = ((long long)nitems + 7) / 8;
        int blocks = (int)((want + 127) / 128);
        scatter_ldg_kernel<<<blocks, 128>>>((const float4*)H, idx, out,
                                            nitems, node_num);
    }
}

// round 11
// speedup vs baseline: 3.8644x; 1.1356x over previous
#include <cuda_runtime.h>
#include <cstdint>

// AggrSum: out[n, :] = sum over edges e with X_node[e] == n of H[e, :]
// H: [2M, 32] f32, X_node: [2M] i32 (harness downcast), out: [100K, 32] f32
//
// R11: occupancy-tuned RED scatter (the winning structure from R4).
//  - item = (edge, float4-offset); strided mapping keeps H loads 128B-coalesced
//    and gives each warp 4-line-coalesced RED.v4 targets (8 lanes per node row).
//  - UNROLL=4 (16 data regs) + __launch_bounds__(256,6) -> ~48 warps/SM
//    (vs 32 at R4's 56 regs) for better DRAM latency hiding.
//  - red.global.add.v4.f32: no-return RMW resolved at L2 (out is L2-resident).
//  - zero kernel: one store per thread, exact cover (proven ~1us incl. gap).

static constexpr int D = 32;
static constexpr int VEC = 4;
static constexpr int LANES = D / VEC;   // 8 float4s per edge row
static constexpr int UNROLL = 4;
static constexpr int THREADS = 256;

__global__ void zero_out_kernel(float4* __restrict__ out, int n4) {
    int i = blockIdx.x * blockDim.x + threadIdx.x;
    if (i < n4) out[i] = make_float4(0.f, 0.f, 0.f, 0.f);
}

__device__ __forceinline__ void red_add_v4(float* dst, float4 v) {
    asm volatile("red.global.add.v4.f32 [%0], {%1, %2, %3, %4};"
                 :: "l"(dst), "f"(v.x), "f"(v.y), "f"(v.z), "f"(v.w)
                 : "memory");
}

__global__ void __launch_bounds__(THREADS, 6)
scatter_add_kernel(const float4* __restrict__ H,
                   const int* __restrict__ idx,
                   float* __restrict__ out,
                   int nitems, int node_num) {
    const int T = gridDim.x * blockDim.x;   // stride between a thread's items
    const int t = blockIdx.x * blockDim.x + threadIdx.x;

    if (t + 3 * T < nitems) {
        // Fast path (always taken at the bench shape): 4 independent
        // LDG.128 + 4 broadcast idx loads front-batched, then 4 REDs.
        float4 v0 = __ldcs(&H[t]);
        float4 v1 = __ldcs(&H[t + T]);
        float4 v2 = __ldcs(&H[t + 2 * T]);
        float4 v3 = __ldcs(&H[t + 3 * T]);
        int n0 = __ldg(&idx[t >> 3]);
        int n1 = __ldg(&idx[(t + T) >> 3]);
        int n2 = __ldg(&idx[(t + 2 * T) >> 3]);
        int n3 = __ldg(&idx[(t + 3 * T) >> 3]);

        if ((unsigned)n0 < (unsigned)node_num)
            red_add_v4(out + (size_t)(unsigned)n0 * D + (t & (LANES - 1)) * VEC, v0);
        if ((unsigned)n1 < (unsigned)node_num)
            red_add_v4(out + (size_t)(unsigned)n1 * D + ((t + T) & (LANES - 1)) * VEC, v1);
        if ((unsigned)n2 < (unsigned)node_num)
            red_add_v4(out + (size_t)(unsigned)n2 * D + ((t + 2 * T) & (LANES - 1)) * VEC, v2);
        if ((unsigned)n3 < (unsigned)node_num)
            red_add_v4(out + (size_t)(unsigned)n3 * D + ((t + 3 * T) & (LANES - 1)) * VEC, v3);
    } else {
        // Tail (not taken when nitems % (T*UNROLL) == 0).
        #pragma unroll
        for (int k = 0; k < UNROLL; k++) {
            int i = t + k * T;
            if (i < nitems) {
                float4 v = __ldcs(&H[i]);
                int n = __ldg(&idx[i >> 3]);
                if ((unsigned)n < (unsigned)node_num)
                    red_add_v4(out + (size_t)(unsigned)n * D + (i & (LANES - 1)) * VEC, v);
            }
        }
    }
}

extern "C" void kernel_launch(void* const* d_in, const int* in_sizes, int n_in,
                              void* d_out, int out_size) {
    const float4* H = (const float4*)d_in[0];
    const int* idx = (const int*)d_in[1];
    float* out = (float*)d_out;

    int num_edges = in_sizes[0] / D;
    int node_num = out_size / D;
    int nitems = num_edges * LANES;   // 16M float4 items at the bench shape

    // 1) zero output (poisoned to 0xAA). One float4 store per thread.
    {
        int n4 = out_size / VEC;
        int blocks = (n4 + THREADS - 1) / THREADS;
        zero_out_kernel<<<blocks, THREADS>>>((float4*)d_out, n4);
    }

    // 2) scatter-add: exact cover, one 4-item batch per thread.
    {
        long long want = ((long long)nitems + UNROLL - 1) / UNROLL;
        int blocks = (int)((want + THREADS - 1) / THREADS);
        scatter_add_kernel<<<blocks, THREADS>>>(H, idx, out, nitems, node_num);
    }
}

// round 12
// speedup vs baseline: 3.8830x; 1.0048x over previous
#include <cuda_runtime.h>
#include <cstdint>

// AggrSum: out[n, :] = sum over edges e with X_node[e] == n of H[e, :]
// H: [2M, 32] f32, X_node: [2M] i32 (harness downcast), out: [100K, 32] f32
//
// R12: R11's proven RED scatter (56.9us, near the L2-atomic/L1tex-wavefront
// structural floor) + cudaMemsetAsync for output zeroing (graph memset node:
// removes the zero-kernel launch + gap, ~3.3us -> ~1.5us overhead).
//
// Structure rationale (measured R2-R11):
//  - scatter beats CSR-gather: random 128B row reads cap at ~55% DRAM (row
//    activate bound), and build adds ~15-20us; scatter reads sequentially.
//  - binder is the RED path itself (L2 atomic slice-cycles + L1tex sector
//    wavefronts), insensitive to occupancy 42-84% and load path (LDG vs TMA).
//  - RED.v4 is width-maximal; warp's RED footprint is sector-minimal
//    (8 lanes cover one 128B node row).

static constexpr int D = 32;
static constexpr int VEC = 4;
static constexpr int LANES = D / VEC;   // 8 float4s per edge row
static constexpr int UNROLL = 4;
static constexpr int THREADS = 256;

__device__ __forceinline__ void red_add_v4(float* dst, float4 v) {
    asm volatile("red.global.add.v4.f32 [%0], {%1, %2, %3, %4};"
                 :: "l"(dst), "f"(v.x), "f"(v.y), "f"(v.z), "f"(v.w)
                 : "memory");
}

__global__ void __launch_bounds__(THREADS, 6)
scatter_add_kernel(const float4* __restrict__ H,
                   const int* __restrict__ idx,
                   float* __restrict__ out,
                   int nitems, int node_num) {
    const int T = gridDim.x * blockDim.x;   // stride between a thread's items
    const int t = blockIdx.x * blockDim.x + threadIdx.x;

    if (t + 3 * T < nitems) {
        // Fast path (always taken at the bench shape): 4 independent
        // LDG.128 + 4 broadcast idx loads front-batched, then 4 REDs.
        float4 v0 = __ldcs(&H[t]);
        float4 v1 = __ldcs(&H[t + T]);
        float4 v2 = __ldcs(&H[t + 2 * T]);
        float4 v3 = __ldcs(&H[t + 3 * T]);
        int n0 = __ldg(&idx[t >> 3]);
        int n1 = __ldg(&idx[(t + T) >> 3]);
        int n2 = __ldg(&idx[(t + 2 * T) >> 3]);
        int n3 = __ldg(&idx[(t + 3 * T) >> 3]);

        if ((unsigned)n0 < (unsigned)node_num)
            red_add_v4(out + (size_t)(unsigned)n0 * D + (t & (LANES - 1)) * VEC, v0);
        if ((unsigned)n1 < (unsigned)node_num)
            red_add_v4(out + (size_t)(unsigned)n1 * D + ((t + T) & (LANES - 1)) * VEC, v1);
        if ((unsigned)n2 < (unsigned)node_num)
            red_add_v4(out + (size_t)(unsigned)n2 * D + ((t + 2 * T) & (LANES - 1)) * VEC, v2);
        if ((unsigned)n3 < (unsigned)node_num)
            red_add_v4(out + (size_t)(unsigned)n3 * D + ((t + 3 * T) & (LANES - 1)) * VEC, v3);
    } else {
        // Tail (not taken when nitems % (T*UNROLL) == 0).
        #pragma unroll
        for (int k = 0; k < UNROLL; k++) {
            int i = t + k * T;
            if (i < nitems) {
                float4 v = __ldcs(&H[i]);
                int n = __ldg(&idx[i >> 3]);
                if ((unsigned)n < (unsigned)node_num)
                    red_add_v4(out + (size_t)(unsigned)n * D + (i & (LANES - 1)) * VEC, v);
            }
        }
    }
}

extern "C" void kernel_launch(void* const* d_in, const int* in_sizes, int n_in,
                              void* d_out, int out_size) {
    const float4* H = (const float4*)d_in[0];
    const int* idx = (const int*)d_in[1];
    float* out = (float*)d_out;

    int num_edges = in_sizes[0] / D;
    int node_num = out_size / D;
    int nitems = num_edges * LANES;   // 16M float4 items at the bench shape

    // 1) zero output (poisoned to 0xAA): graph memset node, no kernel launch.
    cudaMemsetAsync(d_out, 0, (size_t)out_size * sizeof(float));

    // 2) scatter-add: exact cover, one 4-item batch per thread.
    {
        long long want = ((long long)nitems + UNROLL - 1) / UNROLL;
        int blocks = (int)((want + THREADS - 1) / THREADS);
        scatter_add_kernel<<<blocks, THREADS>>>(H, idx, out, nitems, node_num);
    }
}